// round 14
// baseline (speedup 1.0000x reference)
#include <cuda_runtime.h>
#include <math.h>

// Problem constants
#define B_    64
#define L_    512
#define C_    1024
#define NT    7
#define START_ 5
#define STOP_  6
#define NROWS (B_ * L_)   // 32768

// GEMM tiling: 128 rows/block (4 warps x 32 rows), 32-col tiles,
// 4-deep PER-WARP cp.async ring.
#define RPB   128
#define TPB   128
#define KC    32
#define NTILE (C_ / KC)           // 32
#define NSTG  4
#define PADW  36
#define WSTG_BYTES (32 * PADW * 4)               // 4608 per warp-stage
#define SW_OFF     (4 * NSTG * WSTG_BYTES)       // 73728
#define SW_BYTES   (NT * (C_ / 2) * 8)           // 28672
#define SB_OFF     (SW_OFF + SW_BYTES)
#define SMEM_BYTES (SB_OFF + 64)                 // ~102.5 KB -> 2 blocks/SM

// CRF overlay inside the (finished) stage region: needs 30.8 KB < 73.7 KB
#define CRF_EE_OFF   0                            // 16384 B
#define CRF_LAB_OFF  16384                        // 2048 B
#define CRF_MA_OFF   18432                        // 8192 B
#define CRF_MB_OFF   26624                        // 4096 B
#define CRF_SS_OFF   30720                        // 128 B

#define NCHK  32
#define CLEN  16
#define NF128 (L_ * NT / 128)     // 28 pred elements per thread (128 thr)

__device__ float g_nll[B_];
__device__ int   g_batch_cnt[B_];   // zero-init; self-resetting
__device__ int   g_cnt;             // zero-init; self-resetting

__device__ __forceinline__ void ffma2(unsigned long long& d,
                                      unsigned long long a,
                                      unsigned long long b) {
    asm("fma.rn.f32x2 %0, %1, %2, %0;" : "+l"(d) : "l"(a), "l"(b));
}
__device__ __forceinline__ void lds_v2b64(unsigned smem_addr,
                                          unsigned long long& lo,
                                          unsigned long long& hi) {
    asm volatile("ld.shared.v2.b64 {%0, %1}, [%2];"
                 : "=l"(lo), "=l"(hi) : "r"(smem_addr));
}
__device__ __forceinline__ float unpack_sum(unsigned long long v) {
    union { unsigned long long u; float2 f; } cv; cv.u = v;
    return cv.f.x + cv.f.y;
}
__device__ __forceinline__ unsigned smem_u32(const void* p) {
    unsigned a;
    asm("{ .reg .u64 t; cvta.to.shared.u64 t, %1; cvt.u32.u64 %0, t; }"
        : "=r"(a) : "l"(p));
    return a;
}
__device__ __forceinline__ void cp_async16(unsigned dst, const void* src) {
    asm volatile("cp.async.cg.shared.global [%0], [%1], 16;"
                 :: "r"(dst), "l"(src));
}
__device__ __forceinline__ void cp_commit() {
    asm volatile("cp.async.commit_group;");
}
template <int N>
__device__ __forceinline__ void cp_wait() {
    asm volatile("cp.async.wait_group %0;" :: "n"(N));
}

// ---------------------------------------------------------------------------
// Fused kernel: GEMM (all 256 blocks) + per-batch CRF (last arriving block of
// each 4-block batch group) + final reduction (last CRF finisher).
// ---------------------------------------------------------------------------
__global__ void __launch_bounds__(TPB) k_fused(
    const float* __restrict__ X, const int* __restrict__ labels,
    const float* __restrict__ W, const float* __restrict__ bias,
    const float* __restrict__ trans, float* __restrict__ out)
{
    extern __shared__ __align__(16) char dsm[];
    unsigned long long* sW2 = (unsigned long long*)(dsm + SW_OFF);
    float* sb = (float*)(dsm + SB_OFF);
    const unsigned sx_base = smem_u32(dsm);

    __shared__ float sET[8][8];
    __shared__ float sT[49];
    __shared__ float sgred[4];
    __shared__ float svscale, sgold;
    __shared__ int   sticket, slast;

    const int tid  = threadIdx.x;
    const int wid  = tid >> 5;
    const int lane = tid & 31;
    float* pred = out + 1 + NROWS;

    // ================= Phase 1: GEMM =================
    for (int i = tid; i < NT * (C_ / 2); i += TPB)
        sW2[i] = ((const unsigned long long*)W)[i];
    if (tid < NT) sb[tid] = bias[tid];
    __syncthreads();

    {
        const int wrow0 = blockIdx.x * RPB + wid * 32;
        const float* xw = X + (size_t)wrow0 * C_;
        const unsigned wbase = sx_base + wid * (NSTG * WSTG_BYTES);

        #define LOAD_TILE(T, BUF) do {                                      \
            const float* sbse = xw + (T) * KC;                              \
            unsigned dbse = wbase + (BUF) * WSTG_BYTES;                     \
            _Pragma("unroll")                                               \
            for (int i_ = 0; i_ < 8; i_++) {                                \
                int seg_ = i_ * 32 + lane;                                  \
                int r_ = seg_ >> 3, j_ = seg_ & 7;                          \
                cp_async16(dbse + r_ * (PADW * 4) + j_ * 16,                \
                           sbse + (size_t)r_ * C_ + j_ * 4);                \
            }                                                               \
        } while (0)

        LOAD_TILE(0, 0); cp_commit();
        LOAD_TILE(1, 1); cp_commit();
        LOAD_TILE(2, 2); cp_commit();

        unsigned long long acc[NT];
        #pragma unroll
        for (int g = 0; g < NT; g++) acc[g] = 0ull;

        for (int t = 0; t < NTILE; t++) {
            if (t + 3 < NTILE) {
                LOAD_TILE(t + 3, (t + 3) & (NSTG - 1));
                cp_commit();
                cp_wait<3>();
            } else {
                cp_wait<0>();
            }
            __syncwarp();

            const unsigned rbase = sx_base + wid * (NSTG * WSTG_BYTES)
                                 + (t & (NSTG - 1)) * WSTG_BYTES
                                 + lane * (PADW * 4);
            // W as 16-byte vector loads (halves W smem wavefronts)
            const ulonglong2* wrow4 =
                (const ulonglong2*)(sW2 + t * (KC / 2));
            #pragma unroll
            for (int j = 0; j < 8; j++) {
                unsigned long long xlo, xhi;
                lds_v2b64(rbase + j * 16, xlo, xhi);
                #pragma unroll
                for (int g = 0; g < NT; g++) {
                    const ulonglong2 wv = wrow4[g * (C_ / 4) + j];
                    ffma2(acc[g], xlo, wv.x);
                    ffma2(acc[g], xhi, wv.y);
                }
            }
            __syncwarp();
        }

        const int grow = wrow0 + lane;
        #pragma unroll
        for (int g = 0; g < NT; g++)
            pred[(size_t)grow * NT + g] = unpack_sum(acc[g]) + sb[g];
        out[1 + grow] = (float)labels[grow];
        #undef LOAD_TILE
    }

    // ================= Ticket: last of the 4 batch blocks does CRF =========
    __threadfence();
    __syncthreads();
    const int batch = blockIdx.x >> 2;
    if (tid == 0)
        sticket = atomicAdd(&g_batch_cnt[batch], 1);
    __syncthreads();
    if (sticket != 3) return;      // losers exit; no spinning anywhere
    __threadfence();               // acquire: other blocks' pred now visible

    // ================= Phase 2: CRF for this batch (128 threads) ===========
    float* sEE  = (float*)(dsm + CRF_EE_OFF);      // [L][8]
    int*   sLab = (int*)  (dsm + CRF_LAB_OFF);     // [L]
    float (*sMa)[8][8] = (float(*)[8][8])(dsm + CRF_MA_OFF);
    float (*sMb)[8][8] = (float(*)[8][8])(dsm + CRF_MB_OFF);
    float* sS   = (float*)(dsm + CRF_SS_OFF);      // [NCHK]

    const float* pb = pred + (size_t)batch * L_ * NT;

    // MLP-batched fill: 28 independent pred loads + 4 label loads per thread
    {
        float xv[NF128];
        #pragma unroll
        for (int k = 0; k < NF128; k++) xv[k] = pb[tid + k * 128];
        int lv[4];
        #pragma unroll
        for (int k = 0; k < 4; k++) lv[k] = labels[batch * L_ + tid + k * 128];

        #pragma unroll
        for (int k = 0; k < NF128; k++) {
            const int i = tid + k * 128;
            sEE[(i / NT) * 8 + (i % NT)] = __expf(xv[k]);
        }
        #pragma unroll
        for (int k = 0; k < 4; k++) {
            sEE[(tid + k * 128) * 8 + 7] = 0.f;
            sLab[tid + k * 128] = lv[k];
        }
    }
    if (tid < 64) {
        int n = tid >> 3, p = tid & 7;
        sET[n][p] = (n < NT && p < NT) ? __expf(trans[n * NT + p]) : 0.f;
    }
    if (tid < 49) sT[tid] = trans[tid];
    __syncthreads();

    // Stage A: 32 chunks x 16 steps; 128 threads -> each 8-thread group
    // does 2 chunks sequentially.
    {
        const int col = tid & 7;
        float ET[NT][NT];
        #pragma unroll
        for (int n = 0; n < NT; n++)
            #pragma unroll
            for (int p = 0; p < NT; p++) ET[n][p] = sET[n][p];

        #pragma unroll
        for (int half = 0; half < 2; half++) {
            const int chunk = (tid >> 3) + half * 16;
            const int t0 = chunk * CLEN;
            float u[NT];
            #pragma unroll
            for (int n = 0; n < NT; n++)
                u[n] = (col < NT) ? ET[n][col] * sEE[t0 * 8 + n] : 0.f;
            float s = 0.f;

            #pragma unroll 4
            for (int step = 1; step < CLEN; step++) {
                const float* ee = &sEE[(t0 + step) * 8];
                float v[NT];
                #pragma unroll
                for (int n = 0; n < NT; n++) {
                    float a = ET[n][0] * u[0];
                    #pragma unroll
                    for (int p = 1; p < NT; p++) a = fmaf(ET[n][p], u[p], a);
                    v[n] = a * ee[n];
                }
                #pragma unroll
                for (int n = 0; n < NT; n++) u[n] = v[n];

                if ((step & 7) == 7) {
                    float m = u[0];
                    #pragma unroll
                    for (int n = 1; n < NT; n++) m = fmaxf(m, u[n]);
                    m = fmaxf(m, __shfl_xor_sync(0xffffffffu, m, 1));
                    m = fmaxf(m, __shfl_xor_sync(0xffffffffu, m, 2));
                    m = fmaxf(m, __shfl_xor_sync(0xffffffffu, m, 4));
                    if (m > 0.f) {
                        float inv = __frcp_rn(m);
                        #pragma unroll
                        for (int n = 0; n < NT; n++) u[n] *= inv;
                        s += __logf(m);
                    }
                }
            }
            #pragma unroll
            for (int n = 0; n < NT; n++) sMa[chunk][col][n] = u[n];
            sMa[chunk][col][7] = 0.f;
            if (col == 0) sS[chunk] = s;
        }
    }

    // Gold score: 4 tokens per thread (labels in shared; pred L1/L2-hot)
    {
        float acc = 0.f;
        #pragma unroll
        for (int k = 0; k < 4; k++) {
            const int t   = tid + k * 128;
            const int tag = sLab[t];
            const int pt  = (t == 0) ? START_ : sLab[t - 1];
            acc += pb[(size_t)t * NT + tag] + sT[tag * NT + pt];
        }
        #pragma unroll
        for (int o = 16; o > 0; o >>= 1)
            acc += __shfl_xor_sync(0xffffffffu, acc, o);
        if (lane == 0) sgred[wid] = acc;
    }
    __syncthreads();

    if (tid == 0) {
        float g = sgred[0] + sgred[1] + sgred[2] + sgred[3];
        sgold = g + sT[STOP_ * NT + sLab[L_ - 1]];
        float s = 0.f;
        #pragma unroll
        for (int i = 0; i < NCHK; i++) s += sS[i];
        svscale = s;
        g_batch_cnt[batch] = 0;     // reset for next graph replay
    }

    // Tree combine: 5 levels of parallel 8x8 matrix products
    #define TREE_LEVEL(SRC, DST, NPAIR) do {                                \
        for (int idx = tid; idx < (NPAIR) * 64; idx += 128) {               \
            int k_ = idx >> 6, e_ = idx & 63;                               \
            int col_ = e_ >> 3, row_ = e_ & 7;                              \
            const float* A_ = &SRC[2 * k_][col_][0];                        \
            const float* Bv = &SRC[2 * k_ + 1][0][row_];                    \
            float a_ = Bv[0] * A_[0];                                       \
            _Pragma("unroll")                                               \
            for (int j_ = 1; j_ < 8; j_++)                                  \
                a_ = fmaf(Bv[j_ * 8], A_[j_], a_);                          \
            DST[k_][col_][row_] = a_;                                       \
        }                                                                   \
        __syncthreads();                                                    \
    } while (0)

    TREE_LEVEL(sMa, sMb, 16);
    TREE_LEVEL(sMb, sMa, 8);
    TREE_LEVEL(sMa, sMb, 4);
    TREE_LEVEL(sMb, sMa, 2);
    TREE_LEVEL(sMa, sMb, 1);
    #undef TREE_LEVEL

    if (tid == 0) {
        float sum = 0.f;
        #pragma unroll
        for (int n = 0; n < NT; n++)
            sum += sMb[0][START_][n] * sET[STOP_][n];
        g_nll[batch] = __logf(sum) + svscale - sgold;
        __threadfence();
        slast = (atomicAdd(&g_cnt, 1) == B_ - 1);
    }
    __syncthreads();

    // Last CRF finisher: deterministic sum of all 64 NLLs -> out[0]
    if (slast) {
        __shared__ float sred[64];
        __threadfence();
        if (tid < 64) sred[tid] = *((volatile float*)&g_nll[tid]);
        __syncthreads();
        if (tid < 32) sred[tid] += sred[tid + 32];
        __syncthreads();
        if (tid == 0) {
            float s = 0.f;
            #pragma unroll
            for (int i = 0; i < 32; i++) s += sred[i];
            out[0] = s;
            g_cnt = 0;          // reset for next graph replay
        }
    }
}

extern "C" void kernel_launch(void* const* d_in, const int* in_sizes, int n_in,
                              void* d_out, int out_size)
{
    const float* X      = (const float*)d_in[0];
    const int*   labels = (const int*)  d_in[1];
    const float* W      = (const float*)d_in[2];
    const float* bias   = (const float*)d_in[3];
    const float* trans  = (const float*)d_in[4];
    float* out = (float*)d_out;

    static int smem_cfg = 0;
    if (!smem_cfg) {
        cudaFuncSetAttribute(k_fused,
                             cudaFuncAttributeMaxDynamicSharedMemorySize,
                             SMEM_BYTES);
        smem_cfg = 1;
    }

    k_fused<<<NROWS / RPB, TPB, SMEM_BYTES>>>(X, labels, W, bias, trans, out);
}